// round 1
// baseline (speedup 1.0000x reference)
#include <cuda_runtime.h>
#include <cstdint>

// Problem constants
#define BT   16      // B*T
#define SEQ  1024
#define DMODEL 1024
#define NH   16
#define HD   64
#define E3   3072    // 3*DMODEL

// Scratch (allocation-free rule: __device__ globals)
__device__ float g_qkv[(size_t)BT * SEQ * E3];     // [bt, s, 3*D]
__device__ float g_y  [(size_t)BT * SEQ * DMODEL]; // [bt, s, D]

// ---------------------------------------------------------------------------
// SGEMM: C[m,n] = sum_k A[m,k] * W[n,k] + bias[n]   (torch Linear semantics)
// BM=128, BN=64, BK=16, 256 threads, 8x4 per thread.
// M % 128 == 0, N % 64 == 0, K % 16 == 0 for all our shapes.
// ---------------------------------------------------------------------------
#define BM 128
#define BN 64
#define BKK 16
#define TM 8
#define TN 4

__global__ __launch_bounds__(256) void sgemm_bias(
    const float* __restrict__ A, const float* __restrict__ W,
    const float* __restrict__ bias, float* __restrict__ C,
    int M, int N, int K)
{
    __shared__ float As[BKK][BM];
    __shared__ float Bs[BKK][BN];

    const int tid = threadIdx.x;
    const int tx  = tid & 15;   // N direction (16 * TN=4 = 64)
    const int ty  = tid >> 4;   // M direction (16 * TM=8 = 128)
    const int bm  = blockIdx.y * BM;
    const int bn  = blockIdx.x * BN;

    // global load mapping
    const int a_row  = tid >> 1;          // 0..127
    const int a_col0 = (tid & 1) * 8;     // 0 or 8
    const int b_row  = tid >> 2;          // 0..63
    const int b_col0 = (tid & 3) * 4;     // 0,4,8,12

    float acc[TM][TN];
    #pragma unroll
    for (int i = 0; i < TM; i++)
        #pragma unroll
        for (int j = 0; j < TN; j++) acc[i][j] = 0.f;

    const float* Aptr = A + (size_t)(bm + a_row) * K;
    const float* Wptr = W + (size_t)(bn + b_row) * K;

    for (int kt = 0; kt < K; kt += BKK) {
        #pragma unroll
        for (int i = 0; i < 8; i++)
            As[a_col0 + i][a_row] = Aptr[kt + a_col0 + i];
        #pragma unroll
        for (int i = 0; i < 4; i++)
            Bs[b_col0 + i][b_row] = Wptr[kt + b_col0 + i];
        __syncthreads();

        #pragma unroll
        for (int k = 0; k < BKK; k++) {
            float ra[TM], rb[TN];
            #pragma unroll
            for (int i = 0; i < TM; i++) ra[i] = As[k][ty * TM + i];
            #pragma unroll
            for (int j = 0; j < TN; j++) rb[j] = Bs[k][tx * TN + j];
            #pragma unroll
            for (int i = 0; i < TM; i++)
                #pragma unroll
                for (int j = 0; j < TN; j++)
                    acc[i][j] += ra[i] * rb[j];
        }
        __syncthreads();
    }

    #pragma unroll
    for (int i = 0; i < TM; i++) {
        const int row = bm + ty * TM + i;
        float* Crow = C + (size_t)row * N;
        #pragma unroll
        for (int j = 0; j < TN; j++) {
            const int col = bn + tx * TN + j;
            Crow[col] = acc[i][j] + bias[col];
        }
    }
}

// ---------------------------------------------------------------------------
// Attention. Mask recomputed analytically:
//   modality: [0,64):-1(latent) [64,832):0 [832,864):1 [864,896):2 [896,1024):3
//   latent q  -> only latent k
//   other q   -> latent k OR same-modality k
// ---------------------------------------------------------------------------
__device__ __forceinline__ int modality(int i) {
    return (i < 64) ? -1 : (i < 832 ? 0 : (i < 864 ? 1 : (i < 896 ? 2 : 3)));
}

#define TKV 32

__global__ __launch_bounds__(128) void attn_kernel(float* __restrict__ y)
{
    const int bt   = blockIdx.x;
    const int h    = blockIdx.y;
    const int qrow = blockIdx.z * 128 + threadIdx.x;

    const float* base = g_qkv + (size_t)bt * SEQ * E3;

    // Load q (pre-scaled by 1/sqrt(64))
    float q[HD];
    const float* qptr = base + (size_t)qrow * E3 + h * HD;
    #pragma unroll
    for (int d = 0; d < HD; d++) q[d] = qptr[d] * 0.125f;

    float acc[HD];
    #pragma unroll
    for (int d = 0; d < HD; d++) acc[d] = 0.f;
    float mrun = -3.4e38f, l = 0.f;

    __shared__ float Ks[TKV][HD];
    __shared__ float Vs[TKV][HD];

    const int  mq   = modality(qrow);
    const bool qlat = (qrow < 64);

    for (int kt = 0; kt < SEQ; kt += TKV) {
        __syncthreads();
        for (int i = threadIdx.x; i < TKV * HD; i += 128) {
            const int r = i >> 6, c = i & 63;
            const float* kr = base + (size_t)(kt + r) * E3 + h * HD;
            Ks[r][c] = kr[DMODEL + c];       // K block
            Vs[r][c] = kr[2 * DMODEL + c];   // V block
        }
        __syncthreads();

        float sc[TKV];
        float tmax = -3.4e38f;
        #pragma unroll
        for (int j = 0; j < TKV; j++) {
            float s = 0.f;
            #pragma unroll
            for (int d = 0; d < HD; d++) s += q[d] * Ks[j][d];
            const int kidx = kt + j;
            const bool allow = (kidx < 64) || (!qlat && modality(kidx) == mq);
            sc[j] = allow ? s : -3.4e38f;
            tmax  = fmaxf(tmax, sc[j]);
        }

        const float newm = fmaxf(mrun, tmax);
        const float corr = __expf(mrun - newm);
        mrun = newm;
        l *= corr;
        #pragma unroll
        for (int d = 0; d < HD; d++) acc[d] *= corr;

        #pragma unroll
        for (int j = 0; j < TKV; j++) {
            const float p = __expf(sc[j] - newm);
            l += p;
            #pragma unroll
            for (int d = 0; d < HD; d++) acc[d] += p * Vs[j][d];
        }
    }

    const float inv = 1.f / l;
    float* yp = y + (size_t)(bt * SEQ + qrow) * DMODEL + h * HD;
    #pragma unroll
    for (int d = 0; d < HD; d++) yp[d] = acc[d] * inv;
}

// ---------------------------------------------------------------------------
// Launch: qkv gemm -> attention -> out gemm
// inputs: x, w_qkv, b_qkv, w_out, b_out, mask(unused; recomputed analytically)
// ---------------------------------------------------------------------------
extern "C" void kernel_launch(void* const* d_in, const int* in_sizes, int n_in,
                              void* d_out, int out_size)
{
    const float* x     = (const float*)d_in[0];
    const float* w_qkv = (const float*)d_in[1];
    const float* b_qkv = (const float*)d_in[2];
    const float* w_out = (const float*)d_in[3];
    const float* b_out = (const float*)d_in[4];
    float* out = (float*)d_out;

    float* qkv_ptr = nullptr;
    float* y_ptr   = nullptr;
    cudaGetSymbolAddress((void**)&qkv_ptr, g_qkv);
    cudaGetSymbolAddress((void**)&y_ptr,   g_y);

    const int M = BT * SEQ; // 16384

    // 1) QKV projection: [16384,1024] x [3072,1024]^T -> [16384,3072]
    {
        dim3 grid(E3 / BN, M / BM);
        sgemm_bias<<<grid, 256>>>(x, w_qkv, b_qkv, qkv_ptr, M, E3, DMODEL);
    }

    // 2) Attention -> g_y
    {
        dim3 grid(BT, NH, SEQ / 128);
        attn_kernel<<<grid, 128>>>(y_ptr);
    }

    // 3) Output projection: [16384,1024] x [1024,1024]^T -> [16384,1024]
    {
        dim3 grid(DMODEL / BN, M / BM);
        sgemm_bias<<<grid, 256>>>(y_ptr, w_out, b_out, out, M, DMODEL, DMODEL);
    }
}

// round 2
// speedup vs baseline: 1.5683x; 1.5683x over previous
#include <cuda_runtime.h>
#include <cstdint>

// Problem constants
#define BT   16
#define SEQ  1024
#define DMODEL 1024
#define NH   16
#define HD   64
#define E3   3072

// Scratch (allocation-free rule: __device__ globals)
__device__ float g_qkv[(size_t)BT * SEQ * E3];
__device__ float g_y  [(size_t)BT * SEQ * DMODEL];

// ===========================================================================
// TF32 tensor-core GEMM with 3xTF32 split (fp32-accurate)
// C[m,n] = sum_k A[m,k] * W[n,k] + bias[n]
// Block 128x128x32, 256 threads, warp grid 2x4 (warp tile 64x32).
// ===========================================================================
#define BM 128
#define BN 128
#define BK 32
#define LDS_K 36   // BK + 4 pad -> conflict-free fragment loads
#define SMEM_BYTES (2 * (BM + BN) * LDS_K * 4)

__device__ __forceinline__ uint32_t f2tf32(float v) {
    uint32_t r;
    asm("cvt.rna.tf32.f32 %0, %1;" : "=r"(r) : "f"(v));
    return r;
}

#define MMA_TF32(c, a0, a1, a2, a3, b0, b1)                                  \
    asm volatile(                                                            \
        "mma.sync.aligned.m16n8k8.row.col.f32.tf32.tf32.f32 "               \
        "{%0,%1,%2,%3}, {%4,%5,%6,%7}, {%8,%9}, {%0,%1,%2,%3};"             \
        : "+f"(c[0]), "+f"(c[1]), "+f"(c[2]), "+f"(c[3])                     \
        : "r"(a0), "r"(a1), "r"(a2), "r"(a3), "r"(b0), "r"(b1))

__device__ __forceinline__ void cp_async16(uint32_t dst, const void* src) {
    asm volatile("cp.async.cg.shared.global [%0], [%1], 16;" :: "r"(dst), "l"(src));
}

__global__ __launch_bounds__(256) void gemm_tf32(
    const float* __restrict__ A, const float* __restrict__ W,
    const float* __restrict__ bias, float* __restrict__ C,
    int M, int N, int K)
{
    extern __shared__ float s_dyn[];
    float* As = s_dyn;                       // [2][BM][LDS_K]
    float* Ws = s_dyn + 2 * BM * LDS_K;      // [2][BN][LDS_K]

    const int tid  = threadIdx.x;
    const int lane = tid & 31;
    const int warp = tid >> 5;
    const int wm   = warp >> 2;   // 0..1
    const int wn   = warp & 3;    // 0..3
    const int bm   = blockIdx.y * BM;
    const int bn   = blockIdx.x * BN;

    // global->smem mapping (cp.async, 16B per thread, 4 rows-of-32 per tile)
    const int lrow = tid >> 3;        // 0..31
    const int lcol = (tid & 7) * 4;   // 0,4,...,28

    const uint32_t sA_base = (uint32_t)__cvta_generic_to_shared(As);
    const uint32_t sW_base = (uint32_t)__cvta_generic_to_shared(Ws);

    float acc[4][4][4];
    #pragma unroll
    for (int i = 0; i < 4; i++)
        #pragma unroll
        for (int j = 0; j < 4; j++)
            #pragma unroll
            for (int r = 0; r < 4; r++) acc[i][j][r] = 0.f;

    const int ntiles = K / BK;

    // prologue: issue tile 0 into buf 0
    {
        const float* ap = A + (size_t)(bm + lrow) * K + lcol;
        const float* wp = W + (size_t)(bn + lrow) * K + lcol;
        #pragma unroll
        for (int r = 0; r < 4; r++) {
            cp_async16(sA_base + (uint32_t)(((lrow + 32 * r) * LDS_K + lcol) * 4),
                       ap + (size_t)32 * r * K);
            cp_async16(sW_base + (uint32_t)(((lrow + 32 * r) * LDS_K + lcol) * 4),
                       wp + (size_t)32 * r * K);
        }
        asm volatile("cp.async.commit_group;");
    }

    for (int kt = 0; kt < ntiles; kt++) {
        const int buf = kt & 1;

        if (kt + 1 < ntiles) {
            const int nb = buf ^ 1;
            const float* ap = A + (size_t)(bm + lrow) * K + (kt + 1) * BK + lcol;
            const float* wp = W + (size_t)(bn + lrow) * K + (kt + 1) * BK + lcol;
            const uint32_t da = sA_base + (uint32_t)(nb * BM * LDS_K * 4);
            const uint32_t dw = sW_base + (uint32_t)(nb * BN * LDS_K * 4);
            #pragma unroll
            for (int r = 0; r < 4; r++) {
                cp_async16(da + (uint32_t)(((lrow + 32 * r) * LDS_K + lcol) * 4),
                           ap + (size_t)32 * r * K);
                cp_async16(dw + (uint32_t)(((lrow + 32 * r) * LDS_K + lcol) * 4),
                           wp + (size_t)32 * r * K);
            }
            asm volatile("cp.async.commit_group;");
            asm volatile("cp.async.wait_group 1;");
        } else {
            asm volatile("cp.async.wait_group 0;");
        }
        __syncthreads();

        const float* Ab = As + buf * BM * LDS_K;
        const float* Wb = Ws + buf * BN * LDS_K;

        #pragma unroll
        for (int ks = 0; ks < 4; ks++) {
            const int k0 = ks * 8 + (lane & 3);

            // B fragments (hi/lo) for 4 n-tiles
            uint32_t bhi[4][2], blo[4][2];
            #pragma unroll
            for (int j = 0; j < 4; j++) {
                const int n = wn * 32 + j * 8 + (lane >> 2);
                const float v0 = Wb[n * LDS_K + k0];
                const float v1 = Wb[n * LDS_K + k0 + 4];
                bhi[j][0] = f2tf32(v0);
                blo[j][0] = f2tf32(v0 - __uint_as_float(bhi[j][0]));
                bhi[j][1] = f2tf32(v1);
                blo[j][1] = f2tf32(v1 - __uint_as_float(bhi[j][1]));
            }

            #pragma unroll
            for (int i = 0; i < 4; i++) {
                const int r0 = wm * 64 + i * 16 + (lane >> 2);
                const float a0 = Ab[r0 * LDS_K + k0];
                const float a1 = Ab[(r0 + 8) * LDS_K + k0];
                const float a2 = Ab[r0 * LDS_K + k0 + 4];
                const float a3 = Ab[(r0 + 8) * LDS_K + k0 + 4];
                const uint32_t ah0 = f2tf32(a0), ah1 = f2tf32(a1);
                const uint32_t ah2 = f2tf32(a2), ah3 = f2tf32(a3);
                const uint32_t al0 = f2tf32(a0 - __uint_as_float(ah0));
                const uint32_t al1 = f2tf32(a1 - __uint_as_float(ah1));
                const uint32_t al2 = f2tf32(a2 - __uint_as_float(ah2));
                const uint32_t al3 = f2tf32(a3 - __uint_as_float(ah3));

                #pragma unroll
                for (int j = 0; j < 4; j++) {
                    MMA_TF32(acc[i][j], ah0, ah1, ah2, ah3, bhi[j][0], bhi[j][1]);
                    MMA_TF32(acc[i][j], ah0, ah1, ah2, ah3, blo[j][0], blo[j][1]);
                    MMA_TF32(acc[i][j], al0, al1, al2, al3, bhi[j][0], bhi[j][1]);
                }
            }
        }
        __syncthreads();
    }

    // epilogue (+bias)
    #pragma unroll
    for (int i = 0; i < 4; i++) {
        const int r0 = bm + wm * 64 + i * 16 + (lane >> 2);
        #pragma unroll
        for (int j = 0; j < 4; j++) {
            const int c0 = bn + wn * 32 + j * 8 + 2 * (lane & 3);
            const float b0 = bias[c0], b1 = bias[c0 + 1];
            float2 v0 = make_float2(acc[i][j][0] + b0, acc[i][j][1] + b1);
            float2 v1 = make_float2(acc[i][j][2] + b0, acc[i][j][3] + b1);
            *(float2*)&C[(size_t)r0 * N + c0] = v0;
            *(float2*)&C[(size_t)(r0 + 8) * N + c0] = v1;
        }
    }
}

// ===========================================================================
// Attention (unchanged from R0): 1 thread = 1 query row, online softmax,
// analytic modality mask.
// ===========================================================================
__device__ __forceinline__ int modality(int i) {
    return (i < 64) ? -1 : (i < 832 ? 0 : (i < 864 ? 1 : (i < 896 ? 2 : 3)));
}

#define TKV 32

__global__ __launch_bounds__(128) void attn_kernel(float* __restrict__ y)
{
    const int bt   = blockIdx.x;
    const int h    = blockIdx.y;
    const int qrow = blockIdx.z * 128 + threadIdx.x;

    const float* base = g_qkv + (size_t)bt * SEQ * E3;

    float q[HD];
    const float* qptr = base + (size_t)qrow * E3 + h * HD;
    #pragma unroll
    for (int d = 0; d < HD; d++) q[d] = qptr[d] * 0.125f;

    float acc[HD];
    #pragma unroll
    for (int d = 0; d < HD; d++) acc[d] = 0.f;
    float mrun = -3.4e38f, l = 0.f;

    __shared__ float Ks[TKV][HD];
    __shared__ float Vs[TKV][HD];

    const int  mq   = modality(qrow);
    const bool qlat = (qrow < 64);

    for (int kt = 0; kt < SEQ; kt += TKV) {
        __syncthreads();
        for (int i = threadIdx.x; i < TKV * HD; i += 128) {
            const int r = i >> 6, c = i & 63;
            const float* kr = base + (size_t)(kt + r) * E3 + h * HD;
            Ks[r][c] = kr[DMODEL + c];
            Vs[r][c] = kr[2 * DMODEL + c];
        }
        __syncthreads();

        float sc[TKV];
        float tmax = -3.4e38f;
        #pragma unroll
        for (int j = 0; j < TKV; j++) {
            float s = 0.f;
            #pragma unroll
            for (int d = 0; d < HD; d++) s += q[d] * Ks[j][d];
            const int kidx = kt + j;
            const bool allow = (kidx < 64) || (!qlat && modality(kidx) == mq);
            sc[j] = allow ? s : -3.4e38f;
            tmax  = fmaxf(tmax, sc[j]);
        }

        const float newm = fmaxf(mrun, tmax);
        const float corr = __expf(mrun - newm);
        mrun = newm;
        l *= corr;
        #pragma unroll
        for (int d = 0; d < HD; d++) acc[d] *= corr;

        #pragma unroll
        for (int j = 0; j < TKV; j++) {
            const float p = __expf(sc[j] - newm);
            l += p;
            #pragma unroll
            for (int d = 0; d < HD; d++) acc[d] += p * Vs[j][d];
        }
    }

    const float inv = 1.f / l;
    float* yp = y + (size_t)(bt * SEQ + qrow) * DMODEL + h * HD;
    #pragma unroll
    for (int d = 0; d < HD; d++) yp[d] = acc[d] * inv;
}

// ===========================================================================
// Launch
// ===========================================================================
extern "C" void kernel_launch(void* const* d_in, const int* in_sizes, int n_in,
                              void* d_out, int out_size)
{
    const float* x     = (const float*)d_in[0];
    const float* w_qkv = (const float*)d_in[1];
    const float* b_qkv = (const float*)d_in[2];
    const float* w_out = (const float*)d_in[3];
    const float* b_out = (const float*)d_in[4];
    float* out = (float*)d_out;

    float* qkv_ptr = nullptr;
    float* y_ptr   = nullptr;
    cudaGetSymbolAddress((void**)&qkv_ptr, g_qkv);
    cudaGetSymbolAddress((void**)&y_ptr,   g_y);

    cudaFuncSetAttribute(gemm_tf32,
                         cudaFuncAttributeMaxDynamicSharedMemorySize, SMEM_BYTES);

    const int M = BT * SEQ; // 16384

    // 1) QKV projection: [16384,1024] x [3072,1024]^T -> [16384,3072]
    {
        dim3 grid(E3 / BN, M / BM);
        gemm_tf32<<<grid, 256, SMEM_BYTES>>>(x, w_qkv, b_qkv, qkv_ptr, M, E3, DMODEL);
    }

    // 2) Attention -> g_y
    {
        dim3 grid(BT, NH, SEQ / 128);
        attn_kernel<<<grid, 128>>>(y_ptr);
    }

    // 3) Output projection: [16384,1024] x [1024,1024]^T -> [16384,1024]
    {
        dim3 grid(DMODEL / BN, M / BM);
        gemm_tf32<<<grid, 256, SMEM_BYTES>>>(y_ptr, w_out, b_out, out, M, DMODEL, DMODEL);
    }
}

// round 3
// speedup vs baseline: 2.1518x; 1.3721x over previous
#include <cuda_runtime.h>
#include <cstdint>

// Problem constants
#define BT   16
#define SEQ  1024
#define DMODEL 1024
#define NH   16
#define HD   64
#define E3   3072

// Scratch (allocation-free rule: __device__ globals)
__device__ float g_qkv[(size_t)BT * SEQ * E3];
__device__ float g_y  [(size_t)BT * SEQ * DMODEL];

// ===========================================================================
// bf16 3-term split tensor-core GEMM (fp32-accurate to ~1e-5)
// C[m,n] = sum_k A[m,k] * W[n,k] + bias[n]
// Block 128x128x32, 256 threads, warp grid 2x4 (warp tile 64x32).
// Split a = a_hi + a_lo (bf16 each) done at global->shared load time.
// Shared holds packed bf16x2 (k-pairs), stride 20 (conflict-free).
// ===========================================================================
#define BM 128
#define BN 128
#define BK 32
#define KP 16          // k-pairs per row
#define LDSP 20        // padded stride in uint32 (bank-conflict-free)
#define AHI_OFF 0
#define ALO_OFF (128 * LDSP)
#define WHI_OFF (2 * 128 * LDSP)
#define WLO_OFF (3 * 128 * LDSP)
#define BUF_U32 (4 * 128 * LDSP)            // 10240 uint32 per buffer
#define SMEM_BYTES_G (2 * BUF_U32 * 4)      // 81920 bytes

__device__ __forceinline__ uint32_t pack_bf16x2(float lo, float hi) {
    uint32_t r;
    asm("cvt.rn.bf16x2.f32 %0, %1, %2;" : "=r"(r) : "f"(hi), "f"(lo));
    return r;
}

__device__ __forceinline__ void split2(float x, float y, uint32_t& h, uint32_t& l) {
    h = pack_bf16x2(x, y);
    const float hx = __uint_as_float(h << 16);
    const float hy = __uint_as_float(h & 0xffff0000u);
    l = pack_bf16x2(x - hx, y - hy);
}

#define MMA_BF16(c, a0, a1, a2, a3, b0, b1)                                  \
    asm volatile(                                                            \
        "mma.sync.aligned.m16n8k16.row.col.f32.bf16.bf16.f32 "              \
        "{%0,%1,%2,%3}, {%4,%5,%6,%7}, {%8,%9}, {%0,%1,%2,%3};"             \
        : "+f"(c[0]), "+f"(c[1]), "+f"(c[2]), "+f"(c[3])                     \
        : "r"(a0), "r"(a1), "r"(a2), "r"(a3), "r"(b0), "r"(b1))

__global__ __launch_bounds__(256, 1) void gemm_bf16s(
    const float* __restrict__ A, const float* __restrict__ W,
    const float* __restrict__ bias, float* __restrict__ C,
    int M, int N, int K)
{
    extern __shared__ uint32_t sm[];

    const int tid  = threadIdx.x;
    const int lane = tid & 31;
    const int warp = tid >> 5;
    const int wm   = warp >> 2;   // 0..1
    const int wn   = warp & 3;    // 0..3
    const int bm   = blockIdx.y * BM;
    const int bn   = blockIdx.x * BN;

    // loader mapping: each thread loads 4 float4 of A and 4 of W per k-tile
    const int lrow = tid >> 3;        // 0..31
    const int lcol = (tid & 7) * 4;   // float offset 0..28
    const int kp0  = (tid & 7) * 2;   // uint32 (k-pair) offset

    float acc[4][4][4];
    #pragma unroll
    for (int i = 0; i < 4; i++)
        #pragma unroll
        for (int j = 0; j < 4; j++)
            #pragma unroll
            for (int r = 0; r < 4; r++) acc[i][j][r] = 0.f;

    const int ntiles = K / BK;

    float4 stgA[4], stgW[4];
    {
        const float* ap = A + (size_t)(bm + lrow) * K + lcol;
        const float* wp = W + (size_t)(bn + lrow) * K + lcol;
        #pragma unroll
        for (int r = 0; r < 4; r++) {
            stgA[r] = *(const float4*)(ap + (size_t)32 * r * K);
            stgW[r] = *(const float4*)(wp + (size_t)32 * r * K);
        }
    }

    for (int kt = 0; kt < ntiles; kt++) {
        const int base = (kt & 1) * BUF_U32;

        // convert staged registers -> packed bf16x2 hi/lo in shared
        #pragma unroll
        for (int r = 0; r < 4; r++) {
            const int row = lrow + 32 * r;
            uint32_t h0, l0, h1, l1;
            split2(stgA[r].x, stgA[r].y, h0, l0);
            split2(stgA[r].z, stgA[r].w, h1, l1);
            *(uint2*)&sm[base + AHI_OFF + row * LDSP + kp0] = make_uint2(h0, h1);
            *(uint2*)&sm[base + ALO_OFF + row * LDSP + kp0] = make_uint2(l0, l1);
            split2(stgW[r].x, stgW[r].y, h0, l0);
            split2(stgW[r].z, stgW[r].w, h1, l1);
            *(uint2*)&sm[base + WHI_OFF + row * LDSP + kp0] = make_uint2(h0, h1);
            *(uint2*)&sm[base + WLO_OFF + row * LDSP + kp0] = make_uint2(l0, l1);
        }
        __syncthreads();

        // issue next tile's global loads (latency hidden behind MMAs)
        if (kt + 1 < ntiles) {
            const float* ap = A + (size_t)(bm + lrow) * K + (kt + 1) * BK + lcol;
            const float* wp = W + (size_t)(bn + lrow) * K + (kt + 1) * BK + lcol;
            #pragma unroll
            for (int r = 0; r < 4; r++) {
                stgA[r] = *(const float4*)(ap + (size_t)32 * r * K);
                stgW[r] = *(const float4*)(wp + (size_t)32 * r * K);
            }
        }

        // MMAs: 2 k16 steps
        #pragma unroll
        for (int ks = 0; ks < 2; ks++) {
            const int kp = ks * 8 + (lane & 3);

            uint32_t bh[4][2], bl[4][2];
            #pragma unroll
            for (int j = 0; j < 4; j++) {
                const int n = wn * 32 + j * 8 + (lane >> 2);
                bh[j][0] = sm[base + WHI_OFF + n * LDSP + kp];
                bh[j][1] = sm[base + WHI_OFF + n * LDSP + kp + 4];
                bl[j][0] = sm[base + WLO_OFF + n * LDSP + kp];
                bl[j][1] = sm[base + WLO_OFF + n * LDSP + kp + 4];
            }

            #pragma unroll
            for (int i = 0; i < 4; i++) {
                const int r0 = wm * 64 + i * 16 + (lane >> 2);
                const uint32_t ah0 = sm[base + AHI_OFF + r0 * LDSP + kp];
                const uint32_t ah1 = sm[base + AHI_OFF + (r0 + 8) * LDSP + kp];
                const uint32_t ah2 = sm[base + AHI_OFF + r0 * LDSP + kp + 4];
                const uint32_t ah3 = sm[base + AHI_OFF + (r0 + 8) * LDSP + kp + 4];
                const uint32_t al0 = sm[base + ALO_OFF + r0 * LDSP + kp];
                const uint32_t al1 = sm[base + ALO_OFF + (r0 + 8) * LDSP + kp];
                const uint32_t al2 = sm[base + ALO_OFF + r0 * LDSP + kp + 4];
                const uint32_t al3 = sm[base + ALO_OFF + (r0 + 8) * LDSP + kp + 4];

                #pragma unroll
                for (int j = 0; j < 4; j++) {
                    MMA_BF16(acc[i][j], ah0, ah1, ah2, ah3, bh[j][0], bh[j][1]);
                    MMA_BF16(acc[i][j], ah0, ah1, ah2, ah3, bl[j][0], bl[j][1]);
                    MMA_BF16(acc[i][j], al0, al1, al2, al3, bh[j][0], bh[j][1]);
                }
            }
        }
        __syncthreads();
    }

    // epilogue (+bias)
    #pragma unroll
    for (int i = 0; i < 4; i++) {
        const int r0 = bm + wm * 64 + i * 16 + (lane >> 2);
        #pragma unroll
        for (int j = 0; j < 4; j++) {
            const int c0 = bn + wn * 32 + j * 8 + 2 * (lane & 3);
            const float b0 = bias[c0], b1 = bias[c0 + 1];
            float2 v0 = make_float2(acc[i][j][0] + b0, acc[i][j][1] + b1);
            float2 v1 = make_float2(acc[i][j][2] + b0, acc[i][j][3] + b1);
            *(float2*)&C[(size_t)r0 * N + c0] = v0;
            *(float2*)&C[(size_t)(r0 + 8) * N + c0] = v1;
        }
    }
}

// ===========================================================================
// Attention with analytic-mask tile skipping.
//   modality: [0,64):-1 [64,832):0 [832,864):1 [864,896):2 [896,1024):3
//   latent q -> latents only; other q -> latents OR same modality.
// Block z covers q rows [128z, 128z+128). Needed key ranges:
//   z in 0..5 : [0,832)
//   z == 6    : [0,896)
//   z == 7    : [0,64) U [896,1024)
// ===========================================================================
__device__ __forceinline__ int modality(int i) {
    return (i < 64) ? -1 : (i < 832 ? 0 : (i < 864 ? 1 : (i < 896 ? 2 : 3)));
}

#define TKV 32

__global__ __launch_bounds__(128) void attn_kernel(float* __restrict__ y)
{
    const int bt   = blockIdx.x;
    const int h    = blockIdx.y;
    const int bz   = blockIdx.z;
    const int qrow = bz * 128 + threadIdx.x;

    const float* base = g_qkv + (size_t)bt * SEQ * E3;

    float q[HD];
    const float* qptr = base + (size_t)qrow * E3 + h * HD;
    #pragma unroll
    for (int d = 0; d < HD; d++) q[d] = qptr[d] * 0.125f;

    float acc[HD];
    #pragma unroll
    for (int d = 0; d < HD; d++) acc[d] = 0.f;
    float mrun = -3.4e38f, l = 0.f;

    __shared__ float Ks[TKV][HD];
    __shared__ float Vs[TKV][HD];

    const int  mq   = modality(qrow);
    const bool qlat = (qrow < 64);

    int los[2], his[2];
    if (bz < 6)       { los[0] = 0; his[0] = 832; los[1] = 0; his[1] = 0; }
    else if (bz == 6) { los[0] = 0; his[0] = 896; los[1] = 0; his[1] = 0; }
    else              { los[0] = 0; his[0] = 64;  los[1] = 896; his[1] = 1024; }

    for (int rg = 0; rg < 2; rg++) {
        for (int kt = los[rg]; kt < his[rg]; kt += TKV) {
            __syncthreads();
            for (int i = threadIdx.x; i < TKV * HD; i += 128) {
                const int r = i >> 6, c = i & 63;
                const float* kr = base + (size_t)(kt + r) * E3 + h * HD;
                Ks[r][c] = kr[DMODEL + c];
                Vs[r][c] = kr[2 * DMODEL + c];
            }
            __syncthreads();

            float sc[TKV];
            float tmax = -3.4e38f;
            #pragma unroll
            for (int j = 0; j < TKV; j++) {
                float s = 0.f;
                #pragma unroll
                for (int d = 0; d < HD; d++) s += q[d] * Ks[j][d];
                const int kidx = kt + j;
                const bool allow = (kidx < 64) || (!qlat && modality(kidx) == mq);
                sc[j] = allow ? s : -3.4e38f;
                tmax  = fmaxf(tmax, sc[j]);
            }

            const float newm = fmaxf(mrun, tmax);
            const float corr = __expf(mrun - newm);
            mrun = newm;
            l *= corr;
            #pragma unroll
            for (int d = 0; d < HD; d++) acc[d] *= corr;

            #pragma unroll
            for (int j = 0; j < TKV; j++) {
                const float p = __expf(sc[j] - newm);
                l += p;
                #pragma unroll
                for (int d = 0; d < HD; d++) acc[d] += p * Vs[j][d];
            }
        }
    }

    const float inv = 1.f / l;
    float* yp = y + (size_t)(bt * SEQ + qrow) * DMODEL + h * HD;
    #pragma unroll
    for (int d = 0; d < HD; d++) yp[d] = acc[d] * inv;
}

// ===========================================================================
// Launch
// ===========================================================================
extern "C" void kernel_launch(void* const* d_in, const int* in_sizes, int n_in,
                              void* d_out, int out_size)
{
    const float* x     = (const float*)d_in[0];
    const float* w_qkv = (const float*)d_in[1];
    const float* b_qkv = (const float*)d_in[2];
    const float* w_out = (const float*)d_in[3];
    const float* b_out = (const float*)d_in[4];
    float* out = (float*)d_out;

    float* qkv_ptr = nullptr;
    float* y_ptr   = nullptr;
    cudaGetSymbolAddress((void**)&qkv_ptr, g_qkv);
    cudaGetSymbolAddress((void**)&y_ptr,   g_y);

    cudaFuncSetAttribute(gemm_bf16s,
                         cudaFuncAttributeMaxDynamicSharedMemorySize, SMEM_BYTES_G);

    const int M = BT * SEQ; // 16384

    // 1) QKV projection
    {
        dim3 grid(E3 / BN, M / BM);
        gemm_bf16s<<<grid, 256, SMEM_BYTES_G>>>(x, w_qkv, b_qkv, qkv_ptr, M, E3, DMODEL);
    }

    // 2) Attention -> g_y
    {
        dim3 grid(BT, NH, SEQ / 128);
        attn_kernel<<<grid, 128>>>(y_ptr);
    }

    // 3) Output projection
    {
        dim3 grid(DMODEL / BN, M / BM);
        gemm_bf16s<<<grid, 256, SMEM_BYTES_G>>>(y_ptr, w_out, b_out, out, M, DMODEL, DMODEL);
    }
}

// round 4
// speedup vs baseline: 3.9461x; 1.8339x over previous
#include <cuda_runtime.h>
#include <cstdint>

// Problem constants
#define BT   16
#define SEQ  1024
#define DMODEL 1024
#define NH   16
#define HD   64
#define E3   3072

// Scratch: qkv as packed bf16x2 hi/lo (written by QKV GEMM epilogue), y fp32
__device__ uint32_t g_qkv_h[(size_t)BT * SEQ * (E3 / 2)];
__device__ uint32_t g_qkv_l[(size_t)BT * SEQ * (E3 / 2)];
__device__ float    g_y[(size_t)BT * SEQ * DMODEL];

// ===========================================================================
// Common helpers
// ===========================================================================
__device__ __forceinline__ uint32_t pack_bf16x2(float lo, float hi) {
    uint32_t r;
    asm("cvt.rn.bf16x2.f32 %0, %1, %2;" : "=r"(r) : "f"(hi), "f"(lo));
    return r;
}
__device__ __forceinline__ void split2(float x, float y, uint32_t& h, uint32_t& l) {
    h = pack_bf16x2(x, y);
    const float hx = __uint_as_float(h << 16);
    const float hy = __uint_as_float(h & 0xffff0000u);
    l = pack_bf16x2(x - hx, y - hy);
}

#define MMA_BF16(c, a0, a1, a2, a3, b0, b1)                                  \
    asm volatile(                                                            \
        "mma.sync.aligned.m16n8k16.row.col.f32.bf16.bf16.f32 "              \
        "{%0,%1,%2,%3}, {%4,%5,%6,%7}, {%8,%9}, {%0,%1,%2,%3};"             \
        : "+f"(c[0]), "+f"(c[1]), "+f"(c[2]), "+f"(c[3])                     \
        : "r"(a0), "r"(a1), "r"(a2), "r"(a3), "r"(b0), "r"(b1))

__device__ __forceinline__ void cp_async16(uint32_t dst, const void* src) {
    asm volatile("cp.async.cg.shared.global [%0], [%1], 16;" :: "r"(dst), "l"(src));
}
#define CP_COMMIT() asm volatile("cp.async.commit_group;")

#define LDSM_X4_T(r0, r1, r2, r3, addr)                                      \
    asm volatile("ldmatrix.sync.aligned.m8n8.x4.trans.shared.b16 "          \
                 "{%0,%1,%2,%3}, [%4];"                                      \
                 : "=r"(r0), "=r"(r1), "=r"(r2), "=r"(r3) : "r"(addr))

__device__ __forceinline__ int modality(int i) {
    return (i < 64) ? -1 : (i < 832 ? 0 : (i < 864 ? 1 : (i < 896 ? 2 : 3)));
}

// ===========================================================================
// bf16 3-term split GEMM (as R3) with optional split-bf16 output epilogue
// ===========================================================================
#define BM 128
#define BN 128
#define BK 32
#define LDSP 20
#define AHI_OFF 0
#define ALO_OFF (128 * LDSP)
#define WHI_OFF (2 * 128 * LDSP)
#define WLO_OFF (3 * 128 * LDSP)
#define BUF_U32 (4 * 128 * LDSP)
#define SMEM_BYTES_G (2 * BUF_U32 * 4)

template<int SPLIT_OUT>
__global__ __launch_bounds__(256, 1) void gemm_bf16s(
    const float* __restrict__ A, const float* __restrict__ W,
    const float* __restrict__ bias, float* __restrict__ C,
    uint32_t* __restrict__ Ch, uint32_t* __restrict__ Cl,
    int M, int N, int K)
{
    extern __shared__ uint32_t sm[];

    const int tid  = threadIdx.x;
    const int lane = tid & 31;
    const int warp = tid >> 5;
    const int wm   = warp >> 2;
    const int wn   = warp & 3;
    const int bm   = blockIdx.y * BM;
    const int bn   = blockIdx.x * BN;

    const int lrow = tid >> 3;
    const int lcol = (tid & 7) * 4;
    const int kp0  = (tid & 7) * 2;

    float acc[4][4][4];
    #pragma unroll
    for (int i = 0; i < 4; i++)
        #pragma unroll
        for (int j = 0; j < 4; j++)
            #pragma unroll
            for (int r = 0; r < 4; r++) acc[i][j][r] = 0.f;

    const int ntiles = K / BK;

    float4 stgA[4], stgW[4];
    {
        const float* ap = A + (size_t)(bm + lrow) * K + lcol;
        const float* wp = W + (size_t)(bn + lrow) * K + lcol;
        #pragma unroll
        for (int r = 0; r < 4; r++) {
            stgA[r] = *(const float4*)(ap + (size_t)32 * r * K);
            stgW[r] = *(const float4*)(wp + (size_t)32 * r * K);
        }
    }

    for (int kt = 0; kt < ntiles; kt++) {
        const int base = (kt & 1) * BUF_U32;

        #pragma unroll
        for (int r = 0; r < 4; r++) {
            const int row = lrow + 32 * r;
            uint32_t h0, l0, h1, l1;
            split2(stgA[r].x, stgA[r].y, h0, l0);
            split2(stgA[r].z, stgA[r].w, h1, l1);
            *(uint2*)&sm[base + AHI_OFF + row * LDSP + kp0] = make_uint2(h0, h1);
            *(uint2*)&sm[base + ALO_OFF + row * LDSP + kp0] = make_uint2(l0, l1);
            split2(stgW[r].x, stgW[r].y, h0, l0);
            split2(stgW[r].z, stgW[r].w, h1, l1);
            *(uint2*)&sm[base + WHI_OFF + row * LDSP + kp0] = make_uint2(h0, h1);
            *(uint2*)&sm[base + WLO_OFF + row * LDSP + kp0] = make_uint2(l0, l1);
        }
        __syncthreads();

        if (kt + 1 < ntiles) {
            const float* ap = A + (size_t)(bm + lrow) * K + (kt + 1) * BK + lcol;
            const float* wp = W + (size_t)(bn + lrow) * K + (kt + 1) * BK + lcol;
            #pragma unroll
            for (int r = 0; r < 4; r++) {
                stgA[r] = *(const float4*)(ap + (size_t)32 * r * K);
                stgW[r] = *(const float4*)(wp + (size_t)32 * r * K);
            }
        }

        #pragma unroll
        for (int ks = 0; ks < 2; ks++) {
            const int kp = ks * 8 + (lane & 3);

            uint32_t bh[4][2], bl[4][2];
            #pragma unroll
            for (int j = 0; j < 4; j++) {
                const int n = wn * 32 + j * 8 + (lane >> 2);
                bh[j][0] = sm[base + WHI_OFF + n * LDSP + kp];
                bh[j][1] = sm[base + WHI_OFF + n * LDSP + kp + 4];
                bl[j][0] = sm[base + WLO_OFF + n * LDSP + kp];
                bl[j][1] = sm[base + WLO_OFF + n * LDSP + kp + 4];
            }

            #pragma unroll
            for (int i = 0; i < 4; i++) {
                const int r0 = wm * 64 + i * 16 + (lane >> 2);
                const uint32_t ah0 = sm[base + AHI_OFF + r0 * LDSP + kp];
                const uint32_t ah1 = sm[base + AHI_OFF + (r0 + 8) * LDSP + kp];
                const uint32_t ah2 = sm[base + AHI_OFF + r0 * LDSP + kp + 4];
                const uint32_t ah3 = sm[base + AHI_OFF + (r0 + 8) * LDSP + kp + 4];
                const uint32_t al0 = sm[base + ALO_OFF + r0 * LDSP + kp];
                const uint32_t al1 = sm[base + ALO_OFF + (r0 + 8) * LDSP + kp];
                const uint32_t al2 = sm[base + ALO_OFF + r0 * LDSP + kp + 4];
                const uint32_t al3 = sm[base + ALO_OFF + (r0 + 8) * LDSP + kp + 4];

                #pragma unroll
                for (int j = 0; j < 4; j++) {
                    MMA_BF16(acc[i][j], ah0, ah1, ah2, ah3, bh[j][0], bh[j][1]);
                    MMA_BF16(acc[i][j], ah0, ah1, ah2, ah3, bl[j][0], bl[j][1]);
                    MMA_BF16(acc[i][j], al0, al1, al2, al3, bh[j][0], bh[j][1]);
                }
            }
        }
        __syncthreads();
    }

    #pragma unroll
    for (int i = 0; i < 4; i++) {
        const int r0 = bm + wm * 64 + i * 16 + (lane >> 2);
        #pragma unroll
        for (int j = 0; j < 4; j++) {
            const int c0 = bn + wn * 32 + j * 8 + 2 * (lane & 3);
            const float b0 = bias[c0], b1 = bias[c0 + 1];
            const float v0 = acc[i][j][0] + b0, v1 = acc[i][j][1] + b1;
            const float v2 = acc[i][j][2] + b0, v3 = acc[i][j][3] + b1;
            if (SPLIT_OUT) {
                const int np = N >> 1;
                uint32_t h01, l01, h23, l23;
                split2(v0, v1, h01, l01);
                split2(v2, v3, h23, l23);
                Ch[(size_t)r0 * np + (c0 >> 1)] = h01;
                Cl[(size_t)r0 * np + (c0 >> 1)] = l01;
                Ch[(size_t)(r0 + 8) * np + (c0 >> 1)] = h23;
                Cl[(size_t)(r0 + 8) * np + (c0 >> 1)] = l23;
            } else {
                *(float2*)&C[(size_t)r0 * N + c0] = make_float2(v0, v1);
                *(float2*)&C[(size_t)(r0 + 8) * N + c0] = make_float2(v2, v3);
            }
        }
    }
}

// ===========================================================================
// Tensor-core flash attention
// Grid: (BT, NH, 16 q-blocks of 64 rows). 128 threads = 4 warps,
// warp w owns q rows [64z + 16w, +16) (one m16 tile). All modality
// boundaries are 16-aligned -> per-warp uniform modality.
// K/V tiles of 64 keys staged hi/lo bf16 in smem via cp.async (double buf).
// ===========================================================================
#define KB_K_H 0
#define KB_K_L 9216
#define KB_V_H 18432
#define KB_V_L 27648
#define KB_SZ  36864
#define SMEM_BYTES_A (2 * KB_SZ)
#define KST 36          // K smem stride in u32 (32 kpairs + 4 pad)
#define VSTB 144        // V smem row stride in bytes (64 bf16 + 8 pad)

__global__ __launch_bounds__(128, 1) void attn_mma(
    const uint32_t* __restrict__ qh, const uint32_t* __restrict__ ql,
    float* __restrict__ y)
{
    extern __shared__ char smc[];
    const uint32_t smem_u = (uint32_t)__cvta_generic_to_shared(smc);

    const int bt   = blockIdx.x;
    const int h    = blockIdx.y;
    const int z    = blockIdx.z;
    const int tid  = threadIdx.x;
    const int lane = tid & 31;
    const int warp = tid >> 5;

    const int qrow0 = z * 64 + warp * 16;
    const int mq    = modality(qrow0);

    // tile list (starts of 64-key tiles)
    int tl[13];
    int nt;
    if (z == 0)      { tl[0] = 0; nt = 1; }
    else if (z <= 12){ nt = 13; for (int i = 0; i < 13; i++) tl[i] = 64 * i; }
    else if (z == 13){ tl[0] = 0; tl[1] = 832; nt = 2; }
    else             { tl[0] = 0; tl[1] = 896; tl[2] = 960; nt = 3; }

    // ---- Q fragments (hi/lo), held in registers ----
    uint32_t QH[4][4], QL[4][4];
    {
        const size_t rbase = (size_t)(bt * SEQ + qrow0 + (lane >> 2)) * (E3 / 2) + 32 * h;
        const uint32_t* qhp  = qh + rbase;
        const uint32_t* qhp8 = qhp + 8 * (E3 / 2);
        const uint32_t* qlp  = ql + rbase;
        const uint32_t* qlp8 = qlp + 8 * (E3 / 2);
        #pragma unroll
        for (int s = 0; s < 4; s++) {
            const int kp = 8 * s + (lane & 3);
            QH[s][0] = qhp [kp];     QH[s][1] = qhp8[kp];
            QH[s][2] = qhp [kp + 4]; QH[s][3] = qhp8[kp + 4];
            QL[s][0] = qlp [kp];     QL[s][1] = qlp8[kp];
            QL[s][2] = qlp [kp + 4]; QL[s][3] = qlp8[kp + 4];
        }
    }

    float O[8][4];
    #pragma unroll
    for (int j = 0; j < 8; j++)
        #pragma unroll
        for (int e = 0; e < 4; e++) O[j][e] = 0.f;
    float m0 = -1e30f, m1 = -1e30f, l0 = 0.f, l1 = 0.f;

    // loader mapping
    const int lr   = tid >> 1;          // key row 0..63
    const int half = tid & 1;

    // prologue: load tile 0 into buf 0
    {
        const size_t gr = (size_t)(bt * SEQ + tl[0] + lr) * (E3 / 2);
        const uint32_t* kH = qh + gr + 512 + 32 * h;
        const uint32_t* kL = ql + gr + 512 + 32 * h;
        const uint32_t* vH = qh + gr + 1024 + 32 * h;
        const uint32_t* vL = ql + gr + 1024 + 32 * h;
        #pragma unroll
        for (int q = 0; q < 4; q++) {
            const int c4 = half * 4 + q;
            cp_async16(smem_u + KB_K_H + (lr * KST + c4 * 4) * 4, kH + c4 * 4);
            cp_async16(smem_u + KB_K_L + (lr * KST + c4 * 4) * 4, kL + c4 * 4);
            cp_async16(smem_u + KB_V_H + lr * VSTB + c4 * 16, vH + c4 * 4);
            cp_async16(smem_u + KB_V_L + lr * VSTB + c4 * 16, vL + c4 * 4);
        }
        CP_COMMIT();
    }

    for (int it = 0; it < nt; it++) {
        const int kt  = tl[it];
        const uint32_t kb = smem_u + (it & 1) * KB_SZ;

        if (it + 1 < nt) {
            const uint32_t nb = smem_u + ((it + 1) & 1) * KB_SZ;
            const size_t gr = (size_t)(bt * SEQ + tl[it + 1] + lr) * (E3 / 2);
            const uint32_t* kH = qh + gr + 512 + 32 * h;
            const uint32_t* kL = ql + gr + 512 + 32 * h;
            const uint32_t* vH = qh + gr + 1024 + 32 * h;
            const uint32_t* vL = ql + gr + 1024 + 32 * h;
            #pragma unroll
            for (int q = 0; q < 4; q++) {
                const int c4 = half * 4 + q;
                cp_async16(nb + KB_K_H + (lr * KST + c4 * 4) * 4, kH + c4 * 4);
                cp_async16(nb + KB_K_L + (lr * KST + c4 * 4) * 4, kL + c4 * 4);
                cp_async16(nb + KB_V_H + lr * VSTB + c4 * 16, vH + c4 * 4);
                cp_async16(nb + KB_V_L + lr * VSTB + c4 * 16, vL + c4 * 4);
            }
            CP_COMMIT();
            asm volatile("cp.async.wait_group 1;");
        } else {
            asm volatile("cp.async.wait_group 0;");
        }
        __syncthreads();

        const uint32_t* Kh = (const uint32_t*)(smc + (it & 1) * KB_SZ + KB_K_H);
        const uint32_t* Kl = (const uint32_t*)(smc + (it & 1) * KB_SZ + KB_K_L);

        // ---- S = Q K^T (3-term split), scaled & masked ----
        float S[8][4];
        #pragma unroll
        for (int j = 0; j < 8; j++) {
            S[j][0] = S[j][1] = S[j][2] = S[j][3] = 0.f;
            const int n = 8 * j + (lane >> 2);
            #pragma unroll
            for (int s = 0; s < 4; s++) {
                const int kp = 8 * s + (lane & 3);
                const uint32_t bh0 = Kh[n * KST + kp];
                const uint32_t bh1 = Kh[n * KST + kp + 4];
                const uint32_t bl0 = Kl[n * KST + kp];
                const uint32_t bl1 = Kl[n * KST + kp + 4];
                MMA_BF16(S[j], QH[s][0], QH[s][1], QH[s][2], QH[s][3], bh0, bh1);
                MMA_BF16(S[j], QH[s][0], QH[s][1], QH[s][2], QH[s][3], bl0, bl1);
                MMA_BF16(S[j], QL[s][0], QL[s][1], QL[s][2], QL[s][3], bh0, bh1);
            }
        }

        const int cb = kt + 2 * (lane & 3);
        #pragma unroll
        for (int j = 0; j < 8; j++) {
            const int c0 = cb + 8 * j;
            const bool a0 = (c0 < 64) || (modality(c0) == mq);
            const bool a1 = (c0 + 1 < 64) || (modality(c0 + 1) == mq);
            S[j][0] = a0 ? S[j][0] * 0.125f : -1e30f;
            S[j][2] = a0 ? S[j][2] * 0.125f : -1e30f;
            S[j][1] = a1 ? S[j][1] * 0.125f : -1e30f;
            S[j][3] = a1 ? S[j][3] * 0.125f : -1e30f;
        }

        // ---- online softmax ----
        float t0 = -1e30f, t1 = -1e30f;
        #pragma unroll
        for (int j = 0; j < 8; j++) {
            t0 = fmaxf(t0, fmaxf(S[j][0], S[j][1]));
            t1 = fmaxf(t1, fmaxf(S[j][2], S[j][3]));
        }
        t0 = fmaxf(t0, __shfl_xor_sync(0xffffffff, t0, 1));
        t0 = fmaxf(t0, __shfl_xor_sync(0xffffffff, t0, 2));
        t1 = fmaxf(t1, __shfl_xor_sync(0xffffffff, t1, 1));
        t1 = fmaxf(t1, __shfl_xor_sync(0xffffffff, t1, 2));

        const float nm0 = fmaxf(m0, t0), nm1 = fmaxf(m1, t1);
        const float c0f = __expf(m0 - nm0), c1f = __expf(m1 - nm1);
        m0 = nm0; m1 = nm1;
        l0 *= c0f; l1 *= c1f;
        #pragma unroll
        for (int j = 0; j < 8; j++) {
            O[j][0] *= c0f; O[j][1] *= c0f;
            O[j][2] *= c1f; O[j][3] *= c1f;
        }

        #pragma unroll
        for (int j = 0; j < 8; j++) {
            const float p0 = __expf(S[j][0] - nm0);
            const float p1 = __expf(S[j][1] - nm0);
            const float p2 = __expf(S[j][2] - nm1);
            const float p3 = __expf(S[j][3] - nm1);
            l0 += p0 + p1; l1 += p2 + p3;
            S[j][0] = p0; S[j][1] = p1; S[j][2] = p2; S[j][3] = p3;
        }

        // ---- O += P V (3-term split), V via ldmatrix.trans ----
        const uint32_t vhb = kb + KB_V_H;
        const uint32_t vlb = kb + KB_V_L;
        const int lm   = lane >> 3;
        const int lrow8 = (lm & 1) * 8 + (lane & 7);
        const int lcol8 = (lm >> 1) * 8;

        #pragma unroll
        for (int t = 0; t < 4; t++) {
            uint32_t PH[4], PL[4];
            split2(S[2 * t][0],     S[2 * t][1],     PH[0], PL[0]);
            split2(S[2 * t][2],     S[2 * t][3],     PH[1], PL[1]);
            split2(S[2 * t + 1][0], S[2 * t + 1][1], PH[2], PL[2]);
            split2(S[2 * t + 1][2], S[2 * t + 1][3], PH[3], PL[3]);

            const uint32_t rowb = (uint32_t)((16 * t + lrow8) * VSTB);
            #pragma unroll
            for (int np = 0; np < 4; np++) {
                const uint32_t coff = (uint32_t)((np * 16 + lcol8) * 2);
                uint32_t vh0, vh1, vh2, vh3, vl0, vl1, vl2, vl3;
                LDSM_X4_T(vh0, vh1, vh2, vh3, vhb + rowb + coff);
                LDSM_X4_T(vl0, vl1, vl2, vl3, vlb + rowb + coff);
                MMA_BF16(O[2 * np],     PH[0], PH[1], PH[2], PH[3], vh0, vh1);
                MMA_BF16(O[2 * np],     PH[0], PH[1], PH[2], PH[3], vl0, vl1);
                MMA_BF16(O[2 * np],     PL[0], PL[1], PL[2], PL[3], vh0, vh1);
                MMA_BF16(O[2 * np + 1], PH[0], PH[1], PH[2], PH[3], vh2, vh3);
                MMA_BF16(O[2 * np + 1], PH[0], PH[1], PH[2], PH[3], vl2, vl3);
                MMA_BF16(O[2 * np + 1], PL[0], PL[1], PL[2], PL[3], vh2, vh3);
            }
        }
        __syncthreads();
    }

    // ---- finalize ----
    l0 += __shfl_xor_sync(0xffffffff, l0, 1);
    l0 += __shfl_xor_sync(0xffffffff, l0, 2);
    l1 += __shfl_xor_sync(0xffffffff, l1, 1);
    l1 += __shfl_xor_sync(0xffffffff, l1, 2);
    const float i0 = 1.f / l0, i1 = 1.f / l1;

    const int grow = bt * SEQ + qrow0 + (lane >> 2);
    float* yp  = y + (size_t)grow * DMODEL + h * HD;
    float* yp8 = yp + 8 * DMODEL;
    #pragma unroll
    for (int j = 0; j < 8; j++) {
        const int c = 8 * j + 2 * (lane & 3);
        *(float2*)&yp [c] = make_float2(O[j][0] * i0, O[j][1] * i0);
        *(float2*)&yp8[c] = make_float2(O[j][2] * i1, O[j][3] * i1);
    }
}

// ===========================================================================
// Launch
// ===========================================================================
extern "C" void kernel_launch(void* const* d_in, const int* in_sizes, int n_in,
                              void* d_out, int out_size)
{
    const float* x     = (const float*)d_in[0];
    const float* w_qkv = (const float*)d_in[1];
    const float* b_qkv = (const float*)d_in[2];
    const float* w_out = (const float*)d_in[3];
    const float* b_out = (const float*)d_in[4];
    float* out = (float*)d_out;

    uint32_t* qh = nullptr; uint32_t* qlp = nullptr; float* y_ptr = nullptr;
    cudaGetSymbolAddress((void**)&qh,    g_qkv_h);
    cudaGetSymbolAddress((void**)&qlp,   g_qkv_l);
    cudaGetSymbolAddress((void**)&y_ptr, g_y);

    cudaFuncSetAttribute(gemm_bf16s<1>,
                         cudaFuncAttributeMaxDynamicSharedMemorySize, SMEM_BYTES_G);
    cudaFuncSetAttribute(gemm_bf16s<0>,
                         cudaFuncAttributeMaxDynamicSharedMemorySize, SMEM_BYTES_G);
    cudaFuncSetAttribute(attn_mma,
                         cudaFuncAttributeMaxDynamicSharedMemorySize, SMEM_BYTES_A);

    const int M = BT * SEQ;

    // 1) QKV projection -> split bf16 hi/lo
    {
        dim3 grid(E3 / BN, M / BM);
        gemm_bf16s<1><<<grid, 256, SMEM_BYTES_G>>>(x, w_qkv, b_qkv,
                                                   nullptr, qh, qlp, M, E3, DMODEL);
    }

    // 2) Tensor-core attention -> g_y (fp32)
    {
        dim3 grid(BT, NH, 16);
        attn_mma<<<grid, 128, SMEM_BYTES_A>>>(qh, qlp, y_ptr);
    }

    // 3) Output projection -> fp32 out
    {
        dim3 grid(DMODEL / BN, M / BM);
        gemm_bf16s<0><<<grid, 256, SMEM_BYTES_G>>>(y_ptr, w_out, b_out,
                                                   out, nullptr, nullptr, M, DMODEL, DMODEL);
    }
}